// round 4
// baseline (speedup 1.0000x reference)
#include <cuda_runtime.h>
#include <math.h>

#define Bb 4
#define Nn 4096
#define KK 16
#define DP 64
#define DM 128
#define BN (Bb*Nn)
#define EPSV 1e-8f
#define TS 8
#define SS 128           // sAT stride
#define ATHREADS 512

// ---------------- scratch (no allocations allowed) ----------------
__device__ float g_x[BN*DM];
__device__ float g_q[BN*DM];
__device__ float g_k[BN*DM];
__device__ float g_v[BN*DM];
__device__ float g_qn[BN];
__device__ int   g_knn[BN*KK];
__device__ float g_ve[BN*KK*DM];   // v + pos_enc
__device__ float g_r[BN*DM];

// ---------------- packed f32x2 helpers ----------------
__device__ __forceinline__ float2 unpk(unsigned long long v) {
    float2 r;
    asm("mov.b64 {%0, %1}, %2;" : "=f"(r.x), "=f"(r.y) : "l"(v));
    return r;
}

// ---------------- KNN: exact reference arithmetic, stable top-16 ----------------
__global__ void knn_kernel(const float* __restrict__ xyz) {
    extern __shared__ float sm[];
    float* sx = sm;
    float* sy = sm + Nn;
    float* sz = sm + 2*Nn;
    float* ssq = sm + 3*Nn;
    const int b = blockIdx.y;
    const float* base = xyz + (size_t)b*Nn*3;
    for (int m = threadIdx.x; m < Nn; m += blockDim.x) {
        float x = base[m*3+0], y = base[m*3+1], z = base[m*3+2];
        sx[m] = x; sy[m] = y; sz[m] = z;
        float s = __fadd_rn(__fadd_rn(__fmul_rn(x,x), __fmul_rn(y,y)), __fmul_rn(z,z));
        ssq[m] = s;
    }
    __syncthreads();
    const int q = blockIdx.x*blockDim.x + threadIdx.x;
    const float qx = sx[q], qy = sy[q], qz = sz[q], qs = ssq[q];
    float bd[KK]; int bi[KK];
    #pragma unroll
    for (int i=0;i<KK;i++){ bd[i]=3.4e38f; bi[i]=Nn; }
    for (int m=0;m<Nn;m++) {
        float dot = __fmul_rn(qx, sx[m]);
        dot = __fadd_rn(dot, __fmul_rn(qy, sy[m]));
        dot = __fadd_rn(dot, __fmul_rn(qz, sz[m]));
        float d = __fsub_rn(__fadd_rn(qs, ssq[m]), __fmul_rn(2.0f, dot));
        if (d < bd[KK-1]) {
            int j = KK-1;
            while (j > 0 && d < bd[j-1]) { bd[j]=bd[j-1]; bi[j]=bi[j-1]; j--; }
            bd[j]=d; bi[j]=m;
        }
    }
    int* o = g_knn + ((size_t)(b*Nn + q))*KK;
    #pragma unroll
    for (int i=0;i<KK;i++) o[i] = bi[i];
}

// ---------------- x = features @ fc1_w + fc1_b ----------------
__global__ void fc1_kernel(const float* __restrict__ feat,
                           const float* __restrict__ w,
                           const float* __restrict__ bias) {
    int gid = blockIdx.x*blockDim.x + threadIdx.x;      // BN*DM threads
    int row = gid >> 7, c = gid & 127;
    const float* f = feat + (size_t)row*DP;
    float a = 0.f;
    #pragma unroll 8
    for (int d=0; d<DP; d++) a = fmaf(f[d], w[d*DM + c], a);
    g_x[gid] = a + bias[c];
}

// ---------------- q,k,v projections ----------------
__global__ void qkv_kernel(const float* __restrict__ wq,
                           const float* __restrict__ wk,
                           const float* __restrict__ wv) {
    int gid = blockIdx.x*blockDim.x + threadIdx.x;      // BN*DM threads
    int row = gid >> 7, c = gid & 127;
    const float* x = g_x + (size_t)row*DM;
    float aq=0.f, ak=0.f, av=0.f;
    #pragma unroll 4
    for (int d=0; d<DM; d++) {
        float xv = x[d];
        aq = fmaf(xv, wq[d*DM + c], aq);
        ak = fmaf(xv, wk[d*DM + c], ak);
        av = fmaf(xv, wv[d*DM + c], av);
    }
    g_q[gid]=aq; g_k[gid]=ak; g_v[gid]=av;
}

// ---------------- per-row q norm ----------------
__global__ void qn_kernel() {
    int w = (blockIdx.x*blockDim.x + threadIdx.x) >> 5; // one warp per row
    int lane = threadIdx.x & 31;
    const float* q = g_q + (size_t)w*DM;
    float s = 0.f;
    #pragma unroll
    for (int i=lane; i<DM; i+=32) { float v=q[i]; s = fmaf(v,v,s); }
    #pragma unroll
    for (int o=16;o;o>>=1) s += __shfl_xor_sync(0xffffffffu, s, o);
    if (lane==0) g_qn[w] = fmaxf(sqrtf(s), EPSV);
}

// ---------------- packed-FMA GEMM micro-kernel: 4 rows x 8 cols per thread ----------------
__device__ __forceinline__ void gemm_tile2(const float* __restrict__ sAT,
                                           const float* __restrict__ sW,
                                           unsigned long long acc[4][4], int ty, int tx) {
    #pragma unroll 4
    for (int kk=0; kk<DM; kk++) {
        const float4 a0 = *reinterpret_cast<const float4*>(sAT + kk*SS + ty*4);
        const ulonglong2 b0 = *reinterpret_cast<const ulonglong2*>(sW + kk*DM + tx*8);
        const ulonglong2 b1 = *reinterpret_cast<const ulonglong2*>(sW + kk*DM + tx*8 + 4);
        unsigned long long bv[4] = {b0.x, b0.y, b1.x, b1.y};
        float av[4] = {a0.x,a0.y,a0.z,a0.w};
        #pragma unroll
        for (int i=0;i<4;i++) {
            unsigned long long aa;
            asm("mov.b64 %0, {%1, %1};" : "=l"(aa) : "f"(av[i]));
            #pragma unroll
            for (int j=0;j<4;j++)
                asm("fma.rn.f32x2 %0, %1, %2, %0;" : "+l"(acc[i][j]) : "l"(aa), "l"(bv[j]));
        }
    }
}

__global__ void __launch_bounds__(ATHREADS,1) attn_kernel(
    const float* __restrict__ xyz,
    const float* __restrict__ d1_w, const float* __restrict__ d1_b,
    const float* __restrict__ d2_w, const float* __restrict__ d2_b,
    const float* __restrict__ sim_w, const float* __restrict__ sim_b,
    const float* __restrict__ g1_w, const float* __restrict__ g1_b,
    const float* __restrict__ g2_w, const float* __restrict__ g2_b,
    float* __restrict__ attn_out)
{
    extern __shared__ float smf[];
    float* sAT  = smf;                          // [128][128] transposed-input (k-major)
    float* sW   = sAT + DM*SS;                  // [128][128] weights
    float* sSim = sW + DM*DM;                   // [128]
    float* sKKd = sSim + 128;                   // [128] k·k dots
    float* sKxyz = sKKd + 128;                  // [128*3]
    float* sQxyz = sKxyz + 384;                 // [8*3]
    float* sD1  = sQxyz + 24;                   // [512]: w0,w1,w2,b of d1
    __shared__ int sIdx[128];

    const int t = threadIdx.x;
    const int ty = t >> 4;                      // 0..31 -> rows ty*4..+3
    const int tx = t & 15;                      // cols tx*8..+7
    const int tile = blockIdx.x;                // 2048 tiles
    const int b = tile >> 9;
    const int n0 = (tile & 511) * TS;
    const int bn0 = b*Nn + n0;

    if (t < 128) {
        int id = g_knn[(size_t)bn0*KK + t];
        sIdx[t] = id;
        const float* p = xyz + (size_t)(b*Nn + id)*3;
        sKxyz[t*3+0]=p[0]; sKxyz[t*3+1]=p[1]; sKxyz[t*3+2]=p[2];
    } else if (t < 136) {
        int r = t - 128;
        const float* p = xyz + (size_t)(bn0 + r)*3;
        sQxyz[r*3+0]=p[0]; sQxyz[r*3+1]=p[1]; sQxyz[r*3+2]=p[2];
    }
    sD1[t] = (t < 384) ? d1_w[t] : d1_b[t-384];
    // stage d2_w while waiting
    for (int i = t*4; i < DM*DM; i += ATHREADS*4)
        *(float4*)(sW+i) = *(const float4*)(d2_w+i);
    __syncthreads();

    // ---- stage A: h1 = relu(rel_pos @ d1 + b1) -> sAT (k-major: [ch][pr])
    {
        const int pr = t & 127;                 // fixed pair per thread
        const int c0 = t >> 7;                  // 0..3
        const int r = pr >> 4;
        const float rx = sQxyz[r*3+0]-sKxyz[pr*3+0];
        const float ry = sQxyz[r*3+1]-sKxyz[pr*3+1];
        const float rz = sQxyz[r*3+2]-sKxyz[pr*3+2];
        #pragma unroll 8
        for (int i=0;i<32;i++) {
            int ch = i*4 + c0;
            float h = sD1[384+ch];
            h = fmaf(rx, sD1[ch], h);
            h = fmaf(ry, sD1[128+ch], h);
            h = fmaf(rz, sD1[256+ch], h);
            sAT[ch*SS + pr] = fmaxf(h, 0.f);
        }
    }
    __syncthreads();

    unsigned long long acc[4][4];
    float pe[4][8];                             // pos_enc tile in registers

    // ---- GEMM1: pos_enc = h1 @ d2_w
    #pragma unroll
    for (int i=0;i<4;i++)
        #pragma unroll
        for (int j=0;j<4;j++) acc[i][j]=0ull;
    gemm_tile2(sAT, sW, acc, ty, tx);

    // epilogue 1: pe regs; ve = v_gather + pos_enc -> global
    #pragma unroll
    for (int i=0;i<4;i++) {
        int row = ty*4+i;
        #pragma unroll
        for (int j=0;j<4;j++) {
            float2 p = unpk(acc[i][j]);
            pe[i][2*j]   = p.x + d2_b[tx*8+2*j];
            pe[i][2*j+1] = p.y + d2_b[tx*8+2*j+1];
        }
        const float* vp = g_v + (size_t)(b*Nn + sIdx[row])*DM + tx*8;
        float* vep = g_ve + ((size_t)(bn0*KK + row))*DM + tx*8;
        float4 va = *(const float4*)vp;
        float4 vb = *(const float4*)(vp+4);
        *(float4*)vep     = make_float4(va.x+pe[i][0], va.y+pe[i][1], va.z+pe[i][2], va.w+pe[i][3]);
        *(float4*)(vep+4) = make_float4(vb.x+pe[i][4], vb.y+pe[i][5], vb.z+pe[i][6], vb.w+pe[i][7]);
    }
    __syncthreads();

    // ---- stage C: dots, q-k -> sAT, sim_w rows 1.. -> sW
    if (t < 128) {
        const float4* qp = (const float4*)(g_q + (size_t)(bn0 + (t>>4))*DM);
        const float4* kp = (const float4*)(g_k + (size_t)(b*Nn + sIdx[t])*DM);
        float qkdot = 0.f;
        #pragma unroll 8
        for (int c=0;c<32;c++) {
            float4 a = qp[c], k4 = kp[c];
            qkdot = fmaf(a.x,k4.x,qkdot); qkdot = fmaf(a.y,k4.y,qkdot);
            qkdot = fmaf(a.z,k4.z,qkdot); qkdot = fmaf(a.w,k4.w,qkdot);
        }
        sSim[t] = qkdot;   // temp: raw dot
    } else if (t < 256) {
        int p = t-128;
        const float4* kp = (const float4*)(g_k + (size_t)(b*Nn + sIdx[p])*DM);
        float s = 0.f;
        #pragma unroll 8
        for (int c=0;c<32;c++) {
            float4 k4 = kp[c];
            s = fmaf(k4.x,k4.x,s); s = fmaf(k4.y,k4.y,s);
            s = fmaf(k4.z,k4.z,s); s = fmaf(k4.w,k4.w,s);
        }
        sKKd[p] = s;
    }
    {
        const int pr = t & 127;
        const int c0 = t >> 7;
        const float* qrow = g_q + (size_t)(bn0 + (pr>>4))*DM;
        const float* krow = g_k + (size_t)(b*Nn + sIdx[pr])*DM;
        #pragma unroll 8
        for (int i=0;i<32;i++) {
            int ch = i*4 + c0;
            sAT[ch*SS + pr] = qrow[ch] - krow[ch];
        }
    }
    for (int i = t*4; i < DM*DM; i += ATHREADS*4)
        *(float4*)(sW+i) = *(const float4*)(sim_w + DM + i);
    __syncthreads();
    if (t < 128) {
        float kn = fmaxf(sqrtf(sKKd[t]), EPSV);
        float qn = g_qn[bn0 + (t>>4)];
        sSim[t] = sSim[t] / (qn * kn);
    }
    __syncthreads();

    // ---- GEMM2: (q-k) @ sim_w[1:]
    #pragma unroll
    for (int i=0;i<4;i++)
        #pragma unroll
        for (int j=0;j<4;j++) acc[i][j]=0ull;
    gemm_tile2(sAT, sW, acc, ty, tx);
    __syncthreads();

    // epilogue 2: tvals = rel_qk + pos_enc -> sAT (k-major), STS.128 per column
    {
        float sv[4];
        #pragma unroll
        for (int i=0;i<4;i++) sv[i] = sSim[ty*4+i];
        #pragma unroll
        for (int j=0;j<4;j++) {
            int col0 = tx*8 + 2*j;
            float w0 = sim_w[col0], w1 = sim_w[col0+1];
            float b0 = sim_b[col0], b1 = sim_b[col0+1];
            float c0v[4], c1v[4];
            #pragma unroll
            for (int i=0;i<4;i++) {
                float2 p = unpk(acc[i][j]);
                c0v[i] = p.x + sv[i]*w0 + b0 + pe[i][2*j];
                c1v[i] = p.y + sv[i]*w1 + b1 + pe[i][2*j+1];
            }
            *(float4*)(sAT + col0*SS + ty*4)     = make_float4(c0v[0],c0v[1],c0v[2],c0v[3]);
            *(float4*)(sAT + (col0+1)*SS + ty*4) = make_float4(c1v[0],c1v[1],c1v[2],c1v[3]);
        }
    }
    for (int i = t*4; i < DM*DM; i += ATHREADS*4)
        *(float4*)(sW+i) = *(const float4*)(g1_w+i);
    __syncthreads();

    // ---- GEMM3: a1 = relu(t @ g1 + b)
    #pragma unroll
    for (int i=0;i<4;i++)
        #pragma unroll
        for (int j=0;j<4;j++) acc[i][j]=0ull;
    gemm_tile2(sAT, sW, acc, ty, tx);
    __syncthreads();

    #pragma unroll
    for (int j=0;j<4;j++) {
        int col0 = tx*8 + 2*j;
        float b0 = g1_b[col0], b1 = g1_b[col0+1];
        float c0v[4], c1v[4];
        #pragma unroll
        for (int i=0;i<4;i++) {
            float2 p = unpk(acc[i][j]);
            c0v[i] = fmaxf(p.x + b0, 0.f);
            c1v[i] = fmaxf(p.y + b1, 0.f);
        }
        *(float4*)(sAT + col0*SS + ty*4)     = make_float4(c0v[0],c0v[1],c0v[2],c0v[3]);
        *(float4*)(sAT + (col0+1)*SS + ty*4) = make_float4(c1v[0],c1v[1],c1v[2],c1v[3]);
    }
    for (int i = t*4; i < DM*DM; i += ATHREADS*4)
        *(float4*)(sW+i) = *(const float4*)(g2_w+i);
    __syncthreads();

    // ---- GEMM4: attn_pre = a1 @ g2 + b -> d_out attn region
    #pragma unroll
    for (int i=0;i<4;i++)
        #pragma unroll
        for (int j=0;j<4;j++) acc[i][j]=0ull;
    gemm_tile2(sAT, sW, acc, ty, tx);

    #pragma unroll
    for (int i=0;i<4;i++) {
        int row = ty*4+i;
        float* op = attn_out + ((size_t)(bn0*KK + row))*DM + tx*8;
        float o[8];
        #pragma unroll
        for (int j=0;j<4;j++) {
            float2 p = unpk(acc[i][j]);
            o[2*j]   = p.x + g2_b[tx*8+2*j];
            o[2*j+1] = p.y + g2_b[tx*8+2*j+1];
        }
        *(float4*)op     = make_float4(o[0],o[1],o[2],o[3]);
        *(float4*)(op+4) = make_float4(o[4],o[5],o[6],o[7]);
    }
}

// ---------------- softmax over K axis + weighted reduce ----------------
__global__ void softmax_kernel(float* __restrict__ attn) {
    int gid = blockIdx.x*blockDim.x + threadIdx.x;   // BN*DM threads
    int bn = gid >> 7, ch = gid & 127;
    size_t base = (size_t)bn*KK*DM + ch;
    const float sc = 0.08838834764831843f;           // 1/sqrt(128)
    float v[KK];
    float m = -3.4e38f;
    #pragma unroll
    for (int k=0;k<KK;k++){ v[k] = attn[base + k*DM]*sc; m = fmaxf(m, v[k]); }
    float s = 0.f;
    #pragma unroll
    for (int k=0;k<KK;k++){ v[k] = expf(v[k]-m); s += v[k]; }
    float inv = 1.0f/s;
    float r = 0.f;
    #pragma unroll
    for (int k=0;k<KK;k++){
        float a = v[k]*inv;
        attn[base + k*DM] = a;
        r = fmaf(a, g_ve[base + k*DM], r);
    }
    g_r[gid] = r;
}

// ---------------- res = r @ fc2 + b + features ----------------
__global__ void out_kernel(const float* __restrict__ fc2_w, const float* __restrict__ fc2_b,
                           const float* __restrict__ feat, float* __restrict__ res) {
    int gid = blockIdx.x*blockDim.x + threadIdx.x;   // BN*DP threads
    int bn = gid >> 6, c = gid & 63;
    const float* r = g_r + (size_t)bn*DM;
    float a = 0.f;
    #pragma unroll 8
    for (int d=0; d<DM; d++) a = fmaf(r[d], fc2_w[d*DP + c], a);
    res[gid] = a + fc2_b[c] + feat[gid];
}

// ---------------- launch ----------------
extern "C" void kernel_launch(void* const* d_in, const int* in_sizes, int n_in,
                              void* d_out, int out_size) {
    const float* xyz      = (const float*)d_in[0];
    const float* features = (const float*)d_in[1];
    const float* fc1_w = (const float*)d_in[2];
    const float* fc1_b = (const float*)d_in[3];
    const float* fc2_w = (const float*)d_in[4];
    const float* fc2_b = (const float*)d_in[5];
    const float* d1_w  = (const float*)d_in[6];
    const float* d1_b  = (const float*)d_in[7];
    const float* d2_w  = (const float*)d_in[8];
    const float* d2_b  = (const float*)d_in[9];
    const float* g1_w  = (const float*)d_in[10];
    const float* g1_b  = (const float*)d_in[11];
    const float* g2_w  = (const float*)d_in[12];
    const float* g2_b  = (const float*)d_in[13];
    const float* wq_w  = (const float*)d_in[14];
    const float* wk_w  = (const float*)d_in[15];
    const float* wv_w  = (const float*)d_in[16];
    const float* sim_w = (const float*)d_in[17];
    const float* sim_b = (const float*)d_in[18];

    float* res  = (float*)d_out;                       // (B,N,DP)
    float* attn = res + (size_t)BN*DP;                 // (B,N,K,DM)

    const int KNN_SMEM  = 4*Nn*(int)sizeof(float);     // 64 KB
    const int ATTN_SMEM = (DM*SS + DM*DM + 128 + 128 + 384 + 24 + 512)
                          * (int)sizeof(float);        // ~136 KB
    static int attr_done = 0;
    if (!attr_done) {
        cudaFuncSetAttribute(knn_kernel,  cudaFuncAttributeMaxDynamicSharedMemorySize, KNN_SMEM);
        cudaFuncSetAttribute(attn_kernel, cudaFuncAttributeMaxDynamicSharedMemorySize, ATTN_SMEM);
        attr_done = 1;
    }

    knn_kernel<<<dim3(Nn/256, Bb), 256, KNN_SMEM>>>(xyz);
    fc1_kernel<<<(BN*DM)/256, 256>>>(features, fc1_w, fc1_b);
    qkv_kernel<<<(BN*DM)/256, 256>>>(wq_w, wk_w, wv_w);
    qn_kernel<<<BN/8, 256>>>();
    attn_kernel<<<BN/TS, ATHREADS, ATTN_SMEM>>>(xyz, d1_w, d1_b, d2_w, d2_b,
                                                sim_w, sim_b, g1_w, g1_b, g2_w, g2_b, attn);
    softmax_kernel<<<(BN*DM)/256, 256>>>(attn);
    out_kernel<<<(BN*DP)/256, 256>>>(fc2_w, fc2_b, features, res);
}

// round 5
// speedup vs baseline: 1.1988x; 1.1988x over previous
#include <cuda_runtime.h>
#include <math.h>

#define Bb 4
#define Nn 4096
#define KK 16
#define DP 64
#define DM 128
#define BN (Bb*Nn)
#define EPSV 1e-8f
#define TS 8
#define SS 132           // sAT stride (floats); 132%4==0 for float4, bank-stride 4

// ---------------- scratch (no allocations allowed) ----------------
__device__ float g_x[BN*DM];
__device__ float g_q[BN*DM];
__device__ float g_k[BN*DM];
__device__ float g_v[BN*DM];
__device__ float g_qn[BN];
__device__ int   g_knn[BN*KK];
__device__ float g_ve[BN*KK*DM];   // v + pos_enc (L2-hot scratch within attn)
__device__ float g_r[BN*DM];

__device__ __forceinline__ float2 unpk(unsigned long long v) {
    float2 r;
    asm("mov.b64 {%0, %1}, %2;" : "=f"(r.x), "=f"(r.y) : "l"(v));
    return r;
}

// ---------------- KNN: exact reference arithmetic, stable top-16 ----------------
__global__ void knn_kernel(const float* __restrict__ xyz) {
    extern __shared__ float sm[];
    float* sx = sm;
    float* sy = sm + Nn;
    float* sz = sm + 2*Nn;
    float* ssq = sm + 3*Nn;
    const int b = blockIdx.y;
    const float* base = xyz + (size_t)b*Nn*3;
    for (int m = threadIdx.x; m < Nn; m += blockDim.x) {
        float x = base[m*3+0], y = base[m*3+1], z = base[m*3+2];
        sx[m] = x; sy[m] = y; sz[m] = z;
        float s = __fadd_rn(__fadd_rn(__fmul_rn(x,x), __fmul_rn(y,y)), __fmul_rn(z,z));
        ssq[m] = s;
    }
    __syncthreads();
    const int q = blockIdx.x*blockDim.x + threadIdx.x;
    const float qx = sx[q], qy = sy[q], qz = sz[q], qs = ssq[q];
    float bd[KK]; int bi[KK];
    #pragma unroll
    for (int i=0;i<KK;i++){ bd[i]=3.4e38f; bi[i]=Nn; }
    for (int m=0;m<Nn;m++) {
        float dot = __fmul_rn(qx, sx[m]);
        dot = __fadd_rn(dot, __fmul_rn(qy, sy[m]));
        dot = __fadd_rn(dot, __fmul_rn(qz, sz[m]));
        float d = __fsub_rn(__fadd_rn(qs, ssq[m]), __fmul_rn(2.0f, dot));
        if (d < bd[KK-1]) {
            int j = KK-1;
            while (j > 0 && d < bd[j-1]) { bd[j]=bd[j-1]; bi[j]=bi[j-1]; j--; }
            bd[j]=d; bi[j]=m;
        }
    }
    int* o = g_knn + ((size_t)(b*Nn + q))*KK;
    #pragma unroll
    for (int i=0;i<KK;i++) o[i] = bi[i];
}

// ---------------- x = features @ fc1_w + fc1_b (4 cols/thread) ----------------
__global__ void fc1_kernel(const float* __restrict__ feat,
                           const float* __restrict__ w,
                           const float* __restrict__ bias) {
    int gid = blockIdx.x*blockDim.x + threadIdx.x;      // BN*DM/4 threads
    int row = gid >> 5, c4 = (gid & 31)*4;
    const float* f = feat + (size_t)row*DP;
    float4 a = make_float4(0.f,0.f,0.f,0.f);
    #pragma unroll 8
    for (int d=0; d<DP; d++) {
        float fv = f[d];
        float4 w4 = *(const float4*)(w + d*DM + c4);
        a.x = fmaf(fv, w4.x, a.x); a.y = fmaf(fv, w4.y, a.y);
        a.z = fmaf(fv, w4.z, a.z); a.w = fmaf(fv, w4.w, a.w);
    }
    float4 b4 = *(const float4*)(bias + c4);
    a.x+=b4.x; a.y+=b4.y; a.z+=b4.z; a.w+=b4.w;
    *(float4*)(g_x + (size_t)row*DM + c4) = a;
}

// ---------------- q,k,v projections (4 cols/thread, float4 weight loads) ----------------
__global__ void qkv_kernel(const float* __restrict__ wq,
                           const float* __restrict__ wk,
                           const float* __restrict__ wv) {
    int gid = blockIdx.x*blockDim.x + threadIdx.x;      // BN*DM/4 threads
    int row = gid >> 5, c4 = (gid & 31)*4;
    const float* x = g_x + (size_t)row*DM;
    float4 aq = make_float4(0.f,0.f,0.f,0.f);
    float4 ak = aq, av = aq;
    #pragma unroll 4
    for (int d=0; d<DM; d++) {
        float xv = x[d];
        float4 q4 = *(const float4*)(wq + d*DM + c4);
        float4 k4 = *(const float4*)(wk + d*DM + c4);
        float4 v4 = *(const float4*)(wv + d*DM + c4);
        aq.x=fmaf(xv,q4.x,aq.x); aq.y=fmaf(xv,q4.y,aq.y); aq.z=fmaf(xv,q4.z,aq.z); aq.w=fmaf(xv,q4.w,aq.w);
        ak.x=fmaf(xv,k4.x,ak.x); ak.y=fmaf(xv,k4.y,ak.y); ak.z=fmaf(xv,k4.z,ak.z); ak.w=fmaf(xv,k4.w,ak.w);
        av.x=fmaf(xv,v4.x,av.x); av.y=fmaf(xv,v4.y,av.y); av.z=fmaf(xv,v4.z,av.z); av.w=fmaf(xv,v4.w,av.w);
    }
    size_t o = (size_t)row*DM + c4;
    *(float4*)(g_q+o)=aq; *(float4*)(g_k+o)=ak; *(float4*)(g_v+o)=av;
}

// ---------------- per-row q norm ----------------
__global__ void qn_kernel() {
    int w = (blockIdx.x*blockDim.x + threadIdx.x) >> 5;
    int lane = threadIdx.x & 31;
    const float* q = g_q + (size_t)w*DM;
    float s = 0.f;
    #pragma unroll
    for (int i=lane; i<DM; i+=32) { float v=q[i]; s = fmaf(v,v,s); }
    #pragma unroll
    for (int o=16;o;o>>=1) s += __shfl_xor_sync(0xffffffffu, s, o);
    if (lane==0) g_qn[w] = fmaxf(sqrtf(s), EPSV);
}

// ---------------- packed-FMA GEMM micro-kernel: 8 rows x 8 cols per thread ----------------
__device__ __forceinline__ void gemm_tile2(const float* __restrict__ sAT,
                                           const float* __restrict__ sW,
                                           unsigned long long acc[8][4], int ty, int tx) {
    #pragma unroll 4
    for (int kk=0; kk<DM; kk++) {
        const float4 a0 = *reinterpret_cast<const float4*>(sAT + kk*SS + ty*8);
        const float4 a1 = *reinterpret_cast<const float4*>(sAT + kk*SS + ty*8 + 4);
        const ulonglong2 b0 = *reinterpret_cast<const ulonglong2*>(sW + kk*DM + tx*8);
        const ulonglong2 b1 = *reinterpret_cast<const ulonglong2*>(sW + kk*DM + tx*8 + 4);
        unsigned long long bv[4] = {b0.x, b0.y, b1.x, b1.y};
        float av[8] = {a0.x,a0.y,a0.z,a0.w,a1.x,a1.y,a1.z,a1.w};
        #pragma unroll
        for (int i=0;i<8;i++) {
            unsigned long long aa;
            asm("mov.b64 %0, {%1, %1};" : "=l"(aa) : "f"(av[i]));
            #pragma unroll
            for (int j=0;j<4;j++)
                asm("fma.rn.f32x2 %0, %1, %2, %0;" : "+l"(acc[i][j]) : "l"(aa), "l"(bv[j]));
        }
    }
}

__global__ void __launch_bounds__(256,1) attn_kernel(
    const float* __restrict__ xyz,
    const float* __restrict__ d1_w, const float* __restrict__ d1_b,
    const float* __restrict__ d2_w, const float* __restrict__ d2_b,
    const float* __restrict__ sim_w, const float* __restrict__ sim_b,
    const float* __restrict__ g1_w, const float* __restrict__ g1_b,
    const float* __restrict__ g2_w, const float* __restrict__ g2_b,
    float* __restrict__ attn_out)
{
    extern __shared__ float smf[];
    float* sAT   = smf;                 // [128][SS] k-major activations
    float* sW    = sAT + DM*SS;         // [128][128] weights
    float* sQ    = sW + DM*DM;          // [8][128] q rows
    float* sSim  = sQ + 8*DM;           // [128]
    float* sKKd  = sSim + 128;          // [128]
    float* sKxyz = sKKd + 128;          // [128*3]
    float* sQxyz = sKxyz + 384;         // [8*3]
    float* sD1   = sQxyz + 24;          // [512]
    __shared__ int sIdx[128];

    const int t = threadIdx.x;
    const int ty = t >> 4, tx = t & 15;         // rows ty*8..+7, cols tx*8..+7
    const int wrp = t >> 5, lane = t & 31;
    const int tile = blockIdx.x;
    const int b = tile >> 9;
    const int n0 = (tile & 511) * TS;
    const int bn0 = b*Nn + n0;

    // ---- prologue: idx/xyz/d1/sQ + stage d2_w
    if (t < 128) {
        int id = g_knn[(size_t)bn0*KK + t];
        sIdx[t] = id;
        const float* p = xyz + (size_t)(b*Nn + id)*3;
        sKxyz[t*3+0]=p[0]; sKxyz[t*3+1]=p[1]; sKxyz[t*3+2]=p[2];
    } else if (t < 136) {
        int r = t - 128;
        const float* p = xyz + (size_t)(bn0 + r)*3;
        sQxyz[r*3+0]=p[0]; sQxyz[r*3+1]=p[1]; sQxyz[r*3+2]=p[2];
    }
    sD1[t]     = (t < 384) ? d1_w[t] : d1_b[t-384];
    sD1[256+t] = (256+t < 384) ? d1_w[256+t] : d1_b[256+t-384];
    {   // stage q rows coalesced: 8 rows x 128 ch
        int qr = t >> 5, qc = (t & 31)*4;
        *(float4*)(sQ + qr*DM + qc) = *(const float4*)(g_q + (size_t)(bn0+qr)*DM + qc);
    }
    for (int i = t*4; i < DM*DM; i += 1024)
        *(float4*)(sW+i) = *(const float4*)(d2_w+i);
    __syncthreads();

    // ---- stage A: h1 = relu(rel_pos @ d1 + b1) -> sAT (k-major)
    {
        const int pr = t & 127;
        const int c0 = t >> 7;          // 0..1
        const int r = pr >> 4;
        const float rx = sQxyz[r*3+0]-sKxyz[pr*3+0];
        const float ry = sQxyz[r*3+1]-sKxyz[pr*3+1];
        const float rz = sQxyz[r*3+2]-sKxyz[pr*3+2];
        #pragma unroll 8
        for (int i=0;i<64;i++) {
            int ch = i*2 + c0;
            float h = sD1[384+ch];
            h = fmaf(rx, sD1[ch], h);
            h = fmaf(ry, sD1[128+ch], h);
            h = fmaf(rz, sD1[256+ch], h);
            sAT[ch*SS + pr] = fmaxf(h, 0.f);
        }
    }
    __syncthreads();

    unsigned long long acc[8][4];
    float pe[8][8];

    // ---- GEMM1: pos_enc = h1 @ d2_w
    #pragma unroll
    for (int i=0;i<8;i++)
        #pragma unroll
        for (int j=0;j<4;j++) acc[i][j]=0ull;
    gemm_tile2(sAT, sW, acc, ty, tx);

    // epilogue 1: pe regs; ve = v_gather + pos_enc -> g_ve
    #pragma unroll
    for (int i=0;i<8;i++) {
        int row = ty*8+i;
        #pragma unroll
        for (int j=0;j<4;j++) {
            float2 p = unpk(acc[i][j]);
            pe[i][2*j]   = p.x + d2_b[tx*8+2*j];
            pe[i][2*j+1] = p.y + d2_b[tx*8+2*j+1];
        }
        const float* vp = g_v + (size_t)(b*Nn + sIdx[row])*DM + tx*8;
        float* vep = g_ve + ((size_t)(bn0*KK + row))*DM + tx*8;
        float4 va = *(const float4*)vp;
        float4 vb = *(const float4*)(vp+4);
        *(float4*)vep     = make_float4(va.x+pe[i][0], va.y+pe[i][1], va.z+pe[i][2], va.w+pe[i][3]);
        *(float4*)(vep+4) = make_float4(vb.x+pe[i][4], vb.y+pe[i][5], vb.z+pe[i][6], vb.w+pe[i][7]);
    }
    __syncthreads();

    // ---- stage C (coalesced): warp-per-row gather; dots via shfl; q-k -> sAT
    #pragma unroll 2
    for (int r=0; r<16; r++) {
        int pr = wrp*16 + r;
        int nq = pr >> 4;
        const float* krow = g_k + (size_t)(b*Nn + sIdx[pr])*DM;
        float kk = 0.f, qk = 0.f;
        #pragma unroll
        for (int j=0;j<4;j++) {
            int ch = lane + 32*j;
            float kv = krow[ch];             // coalesced 128B per instr
            float qv = sQ[nq*DM + ch];       // conflict-free LDS
            kk = fmaf(kv,kv,kk);
            qk = fmaf(qv,kv,qk);
            sAT[ch*SS + pr] = qv - kv;       // 4-way bank conflict
        }
        #pragma unroll
        for (int o=16;o;o>>=1){ kk += __shfl_xor_sync(0xffffffffu,kk,o);
                                qk += __shfl_xor_sync(0xffffffffu,qk,o); }
        if (lane==0){ sKKd[pr]=kk; sSim[pr]=qk; }
    }
    for (int i = t*4; i < DM*DM; i += 1024)
        *(float4*)(sW+i) = *(const float4*)(sim_w + DM + i);
    __syncthreads();
    if (t < 128) {
        float kn = fmaxf(sqrtf(sKKd[t]), EPSV);
        float qn = g_qn[bn0 + (t>>4)];
        sSim[t] = sSim[t] / (qn * kn);
    }
    __syncthreads();

    // ---- GEMM2: (q-k) @ sim_w[1:]
    #pragma unroll
    for (int i=0;i<8;i++)
        #pragma unroll
        for (int j=0;j<4;j++) acc[i][j]=0ull;
    gemm_tile2(sAT, sW, acc, ty, tx);
    __syncthreads();

    // epilogue 2: tv = rel_qk + pos_enc -> sAT (k-major)
    {
        float tv[8][8];
        #pragma unroll
        for (int i=0;i<8;i++) {
            float sv = sSim[ty*8+i];
            #pragma unroll
            for (int j=0;j<4;j++) {
                float2 p = unpk(acc[i][j]);
                int c0 = tx*8+2*j;
                tv[i][2*j]   = p.x + sv*sim_w[c0]   + sim_b[c0]   + pe[i][2*j];
                tv[i][2*j+1] = p.y + sv*sim_w[c0+1] + sim_b[c0+1] + pe[i][2*j+1];
            }
        }
        #pragma unroll
        for (int c=0;c<8;c++) {
            int col = tx*8+c;
            *(float4*)(sAT + col*SS + ty*8)   = make_float4(tv[0][c],tv[1][c],tv[2][c],tv[3][c]);
            *(float4*)(sAT + col*SS + ty*8+4) = make_float4(tv[4][c],tv[5][c],tv[6][c],tv[7][c]);
        }
    }
    for (int i = t*4; i < DM*DM; i += 1024)
        *(float4*)(sW+i) = *(const float4*)(g1_w+i);
    __syncthreads();

    // ---- GEMM3: a1 = relu(t @ g1 + b)
    #pragma unroll
    for (int i=0;i<8;i++)
        #pragma unroll
        for (int j=0;j<4;j++) acc[i][j]=0ull;
    gemm_tile2(sAT, sW, acc, ty, tx);
    __syncthreads();

    {
        float tv[8][8];
        #pragma unroll
        for (int i=0;i<8;i++)
            #pragma unroll
            for (int j=0;j<4;j++) {
                float2 p = unpk(acc[i][j]);
                int c0 = tx*8+2*j;
                tv[i][2*j]   = fmaxf(p.x + g1_b[c0],   0.f);
                tv[i][2*j+1] = fmaxf(p.y + g1_b[c0+1], 0.f);
            }
        #pragma unroll
        for (int c=0;c<8;c++) {
            int col = tx*8+c;
            *(float4*)(sAT + col*SS + ty*8)   = make_float4(tv[0][c],tv[1][c],tv[2][c],tv[3][c]);
            *(float4*)(sAT + col*SS + ty*8+4) = make_float4(tv[4][c],tv[5][c],tv[6][c],tv[7][c]);
        }
    }
    for (int i = t*4; i < DM*DM; i += 1024)
        *(float4*)(sW+i) = *(const float4*)(g2_w+i);
    __syncthreads();

    // ---- GEMM4: attn_pre = a1 @ g2 + b
    #pragma unroll
    for (int i=0;i<8;i++)
        #pragma unroll
        for (int j=0;j<4;j++) acc[i][j]=0ull;
    gemm_tile2(sAT, sW, acc, ty, tx);

    // ---- fused softmax (over 16 k) + attn write + weighted reduce -> g_r
    {
        const float sc = 0.08838834764831843f;   // 1/sqrt(128)
        float l[8][8];
        #pragma unroll
        for (int i=0;i<8;i++)
            #pragma unroll
            for (int j=0;j<4;j++) {
                float2 p = unpk(acc[i][j]);
                l[i][2*j]   = (p.x + g2_b[tx*8+2*j])*sc;
                l[i][2*j+1] = (p.y + g2_b[tx*8+2*j+1])*sc;
            }
        // thread holds 8 k's of one n (ty even: k0-7; ty odd: k8-15); pair via shfl 16
        float inv[8];
        #pragma unroll
        for (int c=0;c<8;c++) {
            float m = l[0][c];
            #pragma unroll
            for (int i=1;i<8;i++) m = fmaxf(m, l[i][c]);
            m = fmaxf(m, __shfl_xor_sync(0xffffffffu, m, 16));
            float s = 0.f;
            #pragma unroll
            for (int i=0;i<8;i++) { l[i][c] = expf(l[i][c]-m); s += l[i][c]; }
            s += __shfl_xor_sync(0xffffffffu, s, 16);
            inv[c] = 1.0f/s;
        }
        float rp[8];
        #pragma unroll
        for (int c=0;c<8;c++) rp[c]=0.f;
        #pragma unroll
        for (int i=0;i<8;i++) {
            int row = ty*8+i;
            const float* vep = g_ve + ((size_t)(bn0*KK + row))*DM + tx*8;
            float4 va = *(const float4*)vep;
            float4 vb = *(const float4*)(vep+4);
            float vv[8] = {va.x,va.y,va.z,va.w,vb.x,vb.y,vb.z,vb.w};
            float o[8];
            #pragma unroll
            for (int c=0;c<8;c++) {
                float a = l[i][c]*inv[c];
                o[c] = a;
                rp[c] = fmaf(a, vv[c], rp[c]);
            }
            float* op = attn_out + ((size_t)(bn0*KK + row))*DM + tx*8;
            *(float4*)op     = make_float4(o[0],o[1],o[2],o[3]);
            *(float4*)(op+4) = make_float4(o[4],o[5],o[6],o[7]);
        }
        #pragma unroll
        for (int c=0;c<8;c++) rp[c] += __shfl_xor_sync(0xffffffffu, rp[c], 16);
        if ((ty & 1) == 0) {
            int nq = ty >> 1;
            float* rr = g_r + (size_t)(bn0 + nq)*DM + tx*8;
            *(float4*)rr     = make_float4(rp[0],rp[1],rp[2],rp[3]);
            *(float4*)(rr+4) = make_float4(rp[4],rp[5],rp[6],rp[7]);
        }
    }
}

// ---------------- res = r @ fc2 + b + features (4 cols/thread) ----------------
__global__ void out_kernel(const float* __restrict__ fc2_w, const float* __restrict__ fc2_b,
                           const float* __restrict__ feat, float* __restrict__ res) {
    int gid = blockIdx.x*blockDim.x + threadIdx.x;   // BN*DP/4 threads
    int row = gid >> 4, c4 = (gid & 15)*4;
    const float* r = g_r + (size_t)row*DM;
    float4 a = make_float4(0.f,0.f,0.f,0.f);
    #pragma unroll 8
    for (int d=0; d<DM; d++) {
        float rv = r[d];
        float4 w4 = *(const float4*)(fc2_w + d*DP + c4);
        a.x=fmaf(rv,w4.x,a.x); a.y=fmaf(rv,w4.y,a.y);
        a.z=fmaf(rv,w4.z,a.z); a.w=fmaf(rv,w4.w,a.w);
    }
    float4 b4 = *(const float4*)(fc2_b + c4);
    float4 f4 = *(const float4*)(feat + (size_t)row*DP + c4);
    float4 o = make_float4(a.x+b4.x+f4.x, a.y+b4.y+f4.y, a.z+b4.z+f4.z, a.w+b4.w+f4.w);
    *(float4*)(res + (size_t)row*DP + c4) = o;
}

// ---------------- launch ----------------
extern "C" void kernel_launch(void* const* d_in, const int* in_sizes, int n_in,
                              void* d_out, int out_size) {
    const float* xyz      = (const float*)d_in[0];
    const float* features = (const float*)d_in[1];
    const float* fc1_w = (const float*)d_in[2];
    const float* fc1_b = (const float*)d_in[3];
    const float* fc2_w = (const float*)d_in[4];
    const float* fc2_b = (const float*)d_in[5];
    const float* d1_w  = (const float*)d_in[6];
    const float* d1_b  = (const float*)d_in[7];
    const float* d2_w  = (const float*)d_in[8];
    const float* d2_b  = (const float*)d_in[9];
    const float* g1_w  = (const float*)d_in[10];
    const float* g1_b  = (const float*)d_in[11];
    const float* g2_w  = (const float*)d_in[12];
    const float* g2_b  = (const float*)d_in[13];
    const float* wq_w  = (const float*)d_in[14];
    const float* wk_w  = (const float*)d_in[15];
    const float* wv_w  = (const float*)d_in[16];
    const float* sim_w = (const float*)d_in[17];
    const float* sim_b = (const float*)d_in[18];

    float* res  = (float*)d_out;                       // (B,N,DP)
    float* attn = res + (size_t)BN*DP;                 // (B,N,K,DM)

    const int KNN_SMEM  = 4*Nn*(int)sizeof(float);     // 64 KB
    const int ATTN_SMEM = (DM*SS + DM*DM + 8*DM + 128 + 128 + 384 + 24 + 512)
                          * (int)sizeof(float);        // ~142 KB
    static int attr_done = 0;
    if (!attr_done) {
        cudaFuncSetAttribute(knn_kernel,  cudaFuncAttributeMaxDynamicSharedMemorySize, KNN_SMEM);
        cudaFuncSetAttribute(attn_kernel, cudaFuncAttributeMaxDynamicSharedMemorySize, ATTN_SMEM);
        attr_done = 1;
    }

    knn_kernel<<<dim3(Nn/256, Bb), 256, KNN_SMEM>>>(xyz);
    fc1_kernel<<<(BN*DM/4)/256, 256>>>(features, fc1_w, fc1_b);
    qkv_kernel<<<(BN*DM/4)/256, 256>>>(wq_w, wk_w, wv_w);
    qn_kernel<<<BN/8, 256>>>();
    attn_kernel<<<BN/TS, 256, ATTN_SMEM>>>(xyz, d1_w, d1_b, d2_w, d2_b,
                                           sim_w, sim_b, g1_w, g1_b, g2_w, g2_b, attn);
    out_kernel<<<(BN*DP/4)/256, 256>>>(fc2_w, fc2_b, features, res);
}

// round 6
// speedup vs baseline: 1.2597x; 1.0508x over previous
#include <cuda_runtime.h>
#include <math.h>

#define Bb 4
#define Nn 4096
#define KK 16
#define DP 64
#define DM 128
#define BN (Bb*Nn)
#define EPSV 1e-8f
#define TS 8
#define SS 132           // sAT stride (floats)

// ---------------- scratch (no allocations allowed) ----------------
__device__ float g_x[BN*DM];
__device__ float g_q[BN*DM];
__device__ float g_k[BN*DM];
__device__ float g_v[BN*DM];
__device__ float g_qs[BN*DM];      // q @ sim_w[1:]
__device__ float g_ks[BN*DM];      // k @ sim_w[1:]
__device__ float g_qn[BN];
__device__ int   g_knn[BN*KK];
__device__ float g_r[BN*DM];

__device__ __forceinline__ float2 unpk(unsigned long long v) {
    float2 r;
    asm("mov.b64 {%0, %1}, %2;" : "=f"(r.x), "=f"(r.y) : "l"(v));
    return r;
}

// ---------------- KNN: exact reference arithmetic, stable top-16 ----------------
__global__ void knn_kernel(const float* __restrict__ xyz) {
    extern __shared__ float sm[];
    float* sx = sm;
    float* sy = sm + Nn;
    float* sz = sm + 2*Nn;
    float* ssq = sm + 3*Nn;
    const int b = blockIdx.y;
    const float* base = xyz + (size_t)b*Nn*3;
    for (int m = threadIdx.x; m < Nn; m += blockDim.x) {
        float x = base[m*3+0], y = base[m*3+1], z = base[m*3+2];
        sx[m] = x; sy[m] = y; sz[m] = z;
        float s = __fadd_rn(__fadd_rn(__fmul_rn(x,x), __fmul_rn(y,y)), __fmul_rn(z,z));
        ssq[m] = s;
    }
    __syncthreads();
    const int q = blockIdx.x*blockDim.x + threadIdx.x;
    const float qx = sx[q], qy = sy[q], qz = sz[q], qs = ssq[q];
    float bd[KK]; int bi[KK];
    #pragma unroll
    for (int i=0;i<KK;i++){ bd[i]=3.4e38f; bi[i]=Nn; }
    for (int m=0;m<Nn;m++) {
        float dot = __fmul_rn(qx, sx[m]);
        dot = __fadd_rn(dot, __fmul_rn(qy, sy[m]));
        dot = __fadd_rn(dot, __fmul_rn(qz, sz[m]));
        float d = __fsub_rn(__fadd_rn(qs, ssq[m]), __fmul_rn(2.0f, dot));
        if (d < bd[KK-1]) {
            int j = KK-1;
            while (j > 0 && d < bd[j-1]) { bd[j]=bd[j-1]; bi[j]=bi[j-1]; j--; }
            bd[j]=d; bi[j]=m;
        }
    }
    int* o = g_knn + ((size_t)(b*Nn + q))*KK;
    #pragma unroll
    for (int i=0;i<KK;i++) o[i] = bi[i];
}

// ---------------- x = features @ fc1_w + fc1_b (4 cols/thread) ----------------
__global__ void fc1_kernel(const float* __restrict__ feat,
                           const float* __restrict__ w,
                           const float* __restrict__ bias) {
    int gid = blockIdx.x*blockDim.x + threadIdx.x;
    int row = gid >> 5, c4 = (gid & 31)*4;
    const float* f = feat + (size_t)row*DP;
    float4 a = make_float4(0.f,0.f,0.f,0.f);
    #pragma unroll 8
    for (int d=0; d<DP; d++) {
        float fv = f[d];
        float4 w4 = *(const float4*)(w + d*DM + c4);
        a.x = fmaf(fv, w4.x, a.x); a.y = fmaf(fv, w4.y, a.y);
        a.z = fmaf(fv, w4.z, a.z); a.w = fmaf(fv, w4.w, a.w);
    }
    float4 b4 = *(const float4*)(bias + c4);
    a.x+=b4.x; a.y+=b4.y; a.z+=b4.z; a.w+=b4.w;
    *(float4*)(g_x + (size_t)row*DM + c4) = a;
}

// ---------------- q,k,v projections (4 cols/thread) ----------------
__global__ void qkv_kernel(const float* __restrict__ wq,
                           const float* __restrict__ wk,
                           const float* __restrict__ wv) {
    int gid = blockIdx.x*blockDim.x + threadIdx.x;
    int row = gid >> 5, c4 = (gid & 31)*4;
    const float* x = g_x + (size_t)row*DM;
    float4 aq = make_float4(0.f,0.f,0.f,0.f);
    float4 ak = aq, av = aq;
    #pragma unroll 4
    for (int d=0; d<DM; d++) {
        float xv = x[d];
        float4 q4 = *(const float4*)(wq + d*DM + c4);
        float4 k4 = *(const float4*)(wk + d*DM + c4);
        float4 v4 = *(const float4*)(wv + d*DM + c4);
        aq.x=fmaf(xv,q4.x,aq.x); aq.y=fmaf(xv,q4.y,aq.y); aq.z=fmaf(xv,q4.z,aq.z); aq.w=fmaf(xv,q4.w,aq.w);
        ak.x=fmaf(xv,k4.x,ak.x); ak.y=fmaf(xv,k4.y,ak.y); ak.z=fmaf(xv,k4.z,ak.z); ak.w=fmaf(xv,k4.w,ak.w);
        av.x=fmaf(xv,v4.x,av.x); av.y=fmaf(xv,v4.y,av.y); av.z=fmaf(xv,v4.z,av.z); av.w=fmaf(xv,v4.w,av.w);
    }
    size_t o = (size_t)row*DM + c4;
    *(float4*)(g_q+o)=aq; *(float4*)(g_k+o)=ak; *(float4*)(g_v+o)=av;
}

// ---------------- qs = q @ simW1, ks = k @ simW1 (4 cols/thread) ----------------
__global__ void sim_proj_kernel(const float* __restrict__ simw1) {
    int gid = blockIdx.x*blockDim.x + threadIdx.x;
    int row = gid >> 5, c4 = (gid & 31)*4;
    const float* q = g_q + (size_t)row*DM;
    const float* k = g_k + (size_t)row*DM;
    float4 aq = make_float4(0.f,0.f,0.f,0.f);
    float4 ak = aq;
    #pragma unroll 4
    for (int d=0; d<DM; d++) {
        float qv = q[d], kv = k[d];
        float4 w4 = *(const float4*)(simw1 + d*DM + c4);
        aq.x=fmaf(qv,w4.x,aq.x); aq.y=fmaf(qv,w4.y,aq.y); aq.z=fmaf(qv,w4.z,aq.z); aq.w=fmaf(qv,w4.w,aq.w);
        ak.x=fmaf(kv,w4.x,ak.x); ak.y=fmaf(kv,w4.y,ak.y); ak.z=fmaf(kv,w4.z,ak.z); ak.w=fmaf(kv,w4.w,ak.w);
    }
    size_t o = (size_t)row*DM + c4;
    *(float4*)(g_qs+o)=aq; *(float4*)(g_ks+o)=ak;
}

// ---------------- per-row q norm ----------------
__global__ void qn_kernel() {
    int w = (blockIdx.x*blockDim.x + threadIdx.x) >> 5;
    int lane = threadIdx.x & 31;
    const float* q = g_q + (size_t)w*DM;
    float s = 0.f;
    #pragma unroll
    for (int i=lane; i<DM; i+=32) { float v=q[i]; s = fmaf(v,v,s); }
    #pragma unroll
    for (int o=16;o;o>>=1) s += __shfl_xor_sync(0xffffffffu, s, o);
    if (lane==0) g_qn[w] = fmaxf(sqrtf(s), EPSV);
}

// ---------------- packed-FMA GEMM micro-kernel: 8 rows x 8 cols per thread ----------------
__device__ __forceinline__ void gemm_tile2(const float* __restrict__ sAT,
                                           const float* __restrict__ sW,
                                           unsigned long long acc[8][4], int ty, int tx) {
    #pragma unroll 4
    for (int kk=0; kk<DM; kk++) {
        const float4 a0 = *reinterpret_cast<const float4*>(sAT + kk*SS + ty*8);
        const float4 a1 = *reinterpret_cast<const float4*>(sAT + kk*SS + ty*8 + 4);
        const ulonglong2 b0 = *reinterpret_cast<const ulonglong2*>(sW + kk*DM + tx*8);
        const ulonglong2 b1 = *reinterpret_cast<const ulonglong2*>(sW + kk*DM + tx*8 + 4);
        unsigned long long bv[4] = {b0.x, b0.y, b1.x, b1.y};
        float av[8] = {a0.x,a0.y,a0.z,a0.w,a1.x,a1.y,a1.z,a1.w};
        #pragma unroll
        for (int i=0;i<8;i++) {
            unsigned long long aa;
            asm("mov.b64 %0, {%1, %1};" : "=l"(aa) : "f"(av[i]));
            #pragma unroll
            for (int j=0;j<4;j++)
                asm("fma.rn.f32x2 %0, %1, %2, %0;" : "+l"(acc[i][j]) : "l"(aa), "l"(bv[j]));
        }
    }
}

__global__ void __launch_bounds__(256,1) attn_kernel(
    const float* __restrict__ xyz,
    const float* __restrict__ d1_w, const float* __restrict__ d1_b,
    const float* __restrict__ d2_w, const float* __restrict__ d2_b,
    const float* __restrict__ sim_w, const float* __restrict__ sim_b,
    const float* __restrict__ g1_w, const float* __restrict__ g1_b,
    const float* __restrict__ g2_w, const float* __restrict__ g2_b,
    float* __restrict__ attn_out)
{
    extern __shared__ float smf[];
    float* sAT   = smf;                 // [128][SS] k-major activations
    float* sW    = sAT + DM*SS;         // [128][128] weights
    float* sVE   = sW + DM*DM;          // [128][128] v + pos_enc
    float* sQ    = sVE + DM*DM;         // [8][128] q rows
    float* sQS   = sQ + 8*DM;           // [8][128] qs rows
    float* sSim  = sQS + 8*DM;          // [128]
    float* sKKd  = sSim + 128;          // [128]
    float* sKxyz = sKKd + 128;          // [128*3]
    float* sQxyz = sKxyz + 384;         // [8*3]
    float* sD1   = sQxyz + 24;          // [512]
    float* sW0   = sD1 + 512;           // [128] sim_w row 0
    float* sSb   = sW0 + 128;           // [128] sim_b
    __shared__ int sIdx[128];

    const int t = threadIdx.x;
    const int ty = t >> 4, tx = t & 15;
    const int wrp = t >> 5, lane = t & 31;
    const int tile = blockIdx.x;
    const int b = tile >> 9;
    const int n0 = (tile & 511) * TS;
    const int bn0 = b*Nn + n0;

    // ---- prologue
    if (t < 128) {
        int id = g_knn[(size_t)bn0*KK + t];
        sIdx[t] = id;
        const float* p = xyz + (size_t)(b*Nn + id)*3;
        sKxyz[t*3+0]=p[0]; sKxyz[t*3+1]=p[1]; sKxyz[t*3+2]=p[2];
        sW0[t] = sim_w[t];
        sSb[t] = sim_b[t];
    } else if (t < 136) {
        int r = t - 128;
        const float* p = xyz + (size_t)(bn0 + r)*3;
        sQxyz[r*3+0]=p[0]; sQxyz[r*3+1]=p[1]; sQxyz[r*3+2]=p[2];
    }
    sD1[t]     = (t < 384) ? d1_w[t] : d1_b[t-384];
    sD1[256+t] = (256+t < 384) ? d1_w[256+t] : d1_b[256+t-384];
    {   // stage q / qs rows coalesced
        int qr = t >> 5, qc = (t & 31)*4;
        *(float4*)(sQ  + qr*DM + qc) = *(const float4*)(g_q  + (size_t)(bn0+qr)*DM + qc);
        *(float4*)(sQS + qr*DM + qc) = *(const float4*)(g_qs + (size_t)(bn0+qr)*DM + qc);
    }
    for (int i = t*4; i < DM*DM; i += 1024)
        *(float4*)(sW+i) = *(const float4*)(d2_w+i);
    __syncthreads();

    // ---- stage A: h1 = relu(rel_pos @ d1 + b1) -> sAT (k-major)
    {
        const int pr = t & 127;
        const int c0 = t >> 7;
        const int r = pr >> 4;
        const float rx = sQxyz[r*3+0]-sKxyz[pr*3+0];
        const float ry = sQxyz[r*3+1]-sKxyz[pr*3+1];
        const float rz = sQxyz[r*3+2]-sKxyz[pr*3+2];
        #pragma unroll 8
        for (int i=0;i<64;i++) {
            int ch = i*2 + c0;
            float h = sD1[384+ch];
            h = fmaf(rx, sD1[ch], h);
            h = fmaf(ry, sD1[128+ch], h);
            h = fmaf(rz, sD1[256+ch], h);
            sAT[ch*SS + pr] = fmaxf(h, 0.f);
        }
    }
    // ---- stage C: coalesced dots (q.k, k.k) via warp-per-row
    #pragma unroll 2
    for (int r=0; r<16; r++) {
        int pr = wrp*16 + r;
        int nq = pr >> 4;
        const float* krow = g_k + (size_t)(b*Nn + sIdx[pr])*DM;
        float kk = 0.f, qk = 0.f;
        #pragma unroll
        for (int j=0;j<4;j++) {
            int ch = lane + 32*j;
            float kv = krow[ch];
            float qv = sQ[nq*DM + ch];
            kk = fmaf(kv,kv,kk);
            qk = fmaf(qv,kv,qk);
        }
        #pragma unroll
        for (int o=16;o;o>>=1){ kk += __shfl_xor_sync(0xffffffffu,kk,o);
                                qk += __shfl_xor_sync(0xffffffffu,qk,o); }
        if (lane==0){ sKKd[pr]=kk; sSim[pr]=qk; }
    }
    __syncthreads();
    if (t < 128) {
        float kn = fmaxf(sqrtf(sKKd[t]), EPSV);
        float qn = g_qn[bn0 + (t>>4)];
        sSim[t] = sSim[t] / (qn * kn);
    }

    unsigned long long acc[8][4];
    // ---- GEMM1: pos_enc = h1 @ d2_w
    #pragma unroll
    for (int i=0;i<8;i++)
        #pragma unroll
        for (int j=0;j<4;j++) acc[i][j]=0ull;
    gemm_tile2(sAT, sW, acc, ty, tx);
    __syncthreads();    // all reads of h1/sW done; sSim normalized & visible

    // ---- merged epilogue: pe -> ve(sVE), t = pe + qs - ks + sim*w0 + sb -> tv
    {
        float tv[8][8];
        #pragma unroll
        for (int i=0;i<8;i++) {
            int row = ty*8+i;
            float pr8[8];
            #pragma unroll
            for (int j=0;j<4;j++) {
                float2 p = unpk(acc[i][j]);
                pr8[2*j]   = p.x + d2_b[tx*8+2*j];
                pr8[2*j+1] = p.y + d2_b[tx*8+2*j+1];
            }
            const float* vp  = g_v  + (size_t)(b*Nn + sIdx[row])*DM + tx*8;
            const float* ksp = g_ks + (size_t)(b*Nn + sIdx[row])*DM + tx*8;
            float4 va = *(const float4*)vp;
            float4 vb = *(const float4*)(vp+4);
            *(float4*)(sVE + row*DM + tx*8)   = make_float4(va.x+pr8[0], va.y+pr8[1], va.z+pr8[2], va.w+pr8[3]);
            *(float4*)(sVE + row*DM + tx*8+4) = make_float4(vb.x+pr8[4], vb.y+pr8[5], vb.z+pr8[6], vb.w+pr8[7]);
            float4 ka = *(const float4*)ksp;
            float4 kb = *(const float4*)(ksp+4);
            float ks8[8] = {ka.x,ka.y,ka.z,ka.w,kb.x,kb.y,kb.z,kb.w};
            float sv = sSim[row];
            const float* qsrow = sQS + (row>>4)*DM;
            #pragma unroll
            for (int c=0;c<8;c++) {
                int col = tx*8+c;
                tv[i][c] = pr8[c] + qsrow[col] - ks8[c] + sv*sW0[col] + sSb[col];
            }
        }
        #pragma unroll
        for (int c=0;c<8;c++) {
            int col = tx*8+c;
            *(float4*)(sAT + col*SS + ty*8)   = make_float4(tv[0][c],tv[1][c],tv[2][c],tv[3][c]);
            *(float4*)(sAT + col*SS + ty*8+4) = make_float4(tv[4][c],tv[5][c],tv[6][c],tv[7][c]);
        }
    }
    for (int i = t*4; i < DM*DM; i += 1024)
        *(float4*)(sW+i) = *(const float4*)(g1_w+i);
    __syncthreads();

    // ---- GEMM3: a1 = relu(t @ g1 + b)
    #pragma unroll
    for (int i=0;i<8;i++)
        #pragma unroll
        for (int j=0;j<4;j++) acc[i][j]=0ull;
    gemm_tile2(sAT, sW, acc, ty, tx);
    __syncthreads();

    {
        float tv[8][8];
        #pragma unroll
        for (int i=0;i<8;i++)
            #pragma unroll
            for (int j=0;j<4;j++) {
                float2 p = unpk(acc[i][j]);
                int c0 = tx*8+2*j;
                tv[i][2*j]   = fmaxf(p.x + g1_b[c0],   0.f);
                tv[i][2*j+1] = fmaxf(p.y + g1_b[c0+1], 0.f);
            }
        #pragma unroll
        for (int c=0;c<8;c++) {
            int col = tx*8+c;
            *(float4*)(sAT + col*SS + ty*8)   = make_float4(tv[0][c],tv[1][c],tv[2][c],tv[3][c]);
            *(float4*)(sAT + col*SS + ty*8+4) = make_float4(tv[4][c],tv[5][c],tv[6][c],tv[7][c]);
        }
    }
    for (int i = t*4; i < DM*DM; i += 1024)
        *(float4*)(sW+i) = *(const float4*)(g2_w+i);
    __syncthreads();

    // ---- GEMM4: attn_pre = a1 @ g2 + b
    #pragma unroll
    for (int i=0;i<8;i++)
        #pragma unroll
        for (int j=0;j<4;j++) acc[i][j]=0ull;
    gemm_tile2(sAT, sW, acc, ty, tx);

    // ---- fused softmax + attn write + weighted reduce -> g_r
    {
        const float sc = 0.08838834764831843f;   // 1/sqrt(128)
        float l[8][8];
        #pragma unroll
        for (int i=0;i<8;i++)
            #pragma unroll
            for (int j=0;j<4;j++) {
                float2 p = unpk(acc[i][j]);
                l[i][2*j]   = (p.x + g2_b[tx*8+2*j])*sc;
                l[i][2*j+1] = (p.y + g2_b[tx*8+2*j+1])*sc;
            }
        float inv[8];
        #pragma unroll
        for (int c=0;c<8;c++) {
            float m = l[0][c];
            #pragma unroll
            for (int i=1;i<8;i++) m = fmaxf(m, l[i][c]);
            m = fmaxf(m, __shfl_xor_sync(0xffffffffu, m, 16));
            float s = 0.f;
            #pragma unroll
            for (int i=0;i<8;i++) { l[i][c] = expf(l[i][c]-m); s += l[i][c]; }
            s += __shfl_xor_sync(0xffffffffu, s, 16);
            inv[c] = 1.0f/s;
        }
        float rp[8];
        #pragma unroll
        for (int c=0;c<8;c++) rp[c]=0.f;
        #pragma unroll
        for (int i=0;i<8;i++) {
            int row = ty*8+i;
            float4 va = *(float4*)(sVE + row*DM + tx*8);
            float4 vb = *(float4*)(sVE + row*DM + tx*8+4);
            float vv[8] = {va.x,va.y,va.z,va.w,vb.x,vb.y,vb.z,vb.w};
            float o[8];
            #pragma unroll
            for (int c=0;c<8;c++) {
                float a = l[i][c]*inv[c];
                o[c] = a;
                rp[c] = fmaf(a, vv[c], rp[c]);
            }
            float* op = attn_out + ((size_t)(bn0*KK + row))*DM + tx*8;
            *(float4*)op     = make_float4(o[0],o[1],o[2],o[3]);
            *(float4*)(op+4) = make_float4(o[4],o[5],o[6],o[7]);
        }
        #pragma unroll
        for (int c=0;c<8;c++) rp[c] += __shfl_xor_sync(0xffffffffu, rp[c], 16);
        if ((ty & 1) == 0) {
            int nq = ty >> 1;
            float* rr = g_r + (size_t)(bn0 + nq)*DM + tx*8;
            *(float4*)rr     = make_float4(rp[0],rp[1],rp[2],rp[3]);
            *(float4*)(rr+4) = make_float4(rp[4],rp[5],rp[6],rp[7]);
        }
    }
}

// ---------------- res = r @ fc2 + b + features (4 cols/thread) ----------------
__global__ void out_kernel(const float* __restrict__ fc2_w, const float* __restrict__ fc2_b,
                           const float* __restrict__ feat, float* __restrict__ res) {
    int gid = blockIdx.x*blockDim.x + threadIdx.x;
    int row = gid >> 4, c4 = (gid & 15)*4;
    const float* r = g_r + (size_t)row*DM;
    float4 a = make_float4(0.f,0.f,0.f,0.f);
    #pragma unroll 8
    for (int d=0; d<DM; d++) {
        float rv = r[d];
        float4 w4 = *(const float4*)(fc2_w + d*DP + c4);
        a.x=fmaf(rv,w4.x,a.x); a.y=fmaf(rv,w4.y,a.y);
        a.z=fmaf(rv,w4.z,a.z); a.w=fmaf(rv,w4.w,a.w);
    }
    float4 b4 = *(const float4*)(fc2_b + c4);
    float4 f4 = *(const float4*)(feat + (size_t)row*DP + c4);
    float4 o = make_float4(a.x+b4.x+f4.x, a.y+b4.y+f4.y, a.z+b4.z+f4.z, a.w+b4.w+f4.w);
    *(float4*)(res + (size_t)row*DP + c4) = o;
}

// ---------------- launch ----------------
extern "C" void kernel_launch(void* const* d_in, const int* in_sizes, int n_in,
                              void* d_out, int out_size) {
    const float* xyz      = (const float*)d_in[0];
    const float* features = (const float*)d_in[1];
    const float* fc1_w = (const float*)d_in[2];
    const float* fc1_b = (const float*)d_in[3];
    const float* fc2_w = (const float*)d_in[4];
    const float* fc2_b = (const float*)d_in[5];
    const float* d1_w  = (const float*)d_in[6];
    const float* d1_b  = (const float*)d_in[7];
    const float* d2_w  = (const float*)d_in[8];
    const float* d2_b  = (const float*)d_in[9];
    const float* g1_w  = (const float*)d_in[10];
    const float* g1_b  = (const float*)d_in[11];
    const float* g2_w  = (const float*)d_in[12];
    const float* g2_b  = (const float*)d_in[13];
    const float* wq_w  = (const float*)d_in[14];
    const float* wk_w  = (const float*)d_in[15];
    const float* wv_w  = (const float*)d_in[16];
    const float* sim_w = (const float*)d_in[17];
    const float* sim_b = (const float*)d_in[18];

    float* res  = (float*)d_out;                       // (B,N,DP)
    float* attn = res + (size_t)BN*DP;                 // (B,N,K,DM)

    const int KNN_SMEM  = 4*Nn*(int)sizeof(float);     // 64 KB
    const int ATTN_SMEM = (DM*SS + 2*DM*DM + 16*DM + 128 + 128 + 384 + 24 + 512 + 128 + 128)
                          * (int)sizeof(float);        // ~208 KB
    static int attr_done = 0;
    if (!attr_done) {
        cudaFuncSetAttribute(knn_kernel,  cudaFuncAttributeMaxDynamicSharedMemorySize, KNN_SMEM);
        cudaFuncSetAttribute(attn_kernel, cudaFuncAttributeMaxDynamicSharedMemorySize, ATTN_SMEM);
        attr_done = 1;
    }

    knn_kernel<<<dim3(Nn/256, Bb), 256, KNN_SMEM>>>(xyz);
    fc1_kernel<<<(BN*DM/4)/256, 256>>>(features, fc1_w, fc1_b);
    qkv_kernel<<<(BN*DM/4)/256, 256>>>(wq_w, wk_w, wv_w);
    sim_proj_kernel<<<(BN*DM/4)/256, 256>>>(sim_w + DM);
    qn_kernel<<<BN/8, 256>>>();
    attn_kernel<<<BN/TS, 256, ATTN_SMEM>>>(xyz, d1_w, d1_b, d2_w, d2_b,
                                           sim_w, sim_b, g1_w, g1_b, g2_w, g2_b, attn);
    out_kernel<<<(BN*DP/4)/256, 256>>>(fc2_w, fc2_b, features, res);
}